// round 9
// baseline (speedup 1.0000x reference)
#include <cuda_runtime.h>
#include <math.h>
#include <stdint.h>

#define NLEV 16
#define THASH (1u << 19)
#define EBLK 256           // encode block
#define MBLK 128           // mlp block (each thread handles 2 points)
#define NMAX (1 << 20)
#define ACT_STRIDE 68      // 17 float4 -> conflict-free LDS.128
#define WTOT 10436         // 2048 + 4096 + 4096 + 192 + 4
#define NBINS 65536        // 16^4 spatial buckets
#define SBLK 256

struct Res4 { int v[NLEV][4]; };

// Feature scratch (sorted order), level-major.
__device__ float2 g_feat[NLEV][NMAX];
// Sorted copy of x (written by scatter) + permutation for output scatter.
__device__ float4 g_xs[NMAX];
__device__ int g_perm[NMAX];
// Sort scratch.
__device__ int g_hist[NBINS];
__device__ int g_cursor[NBINS];

// ---- packed f32x2 helpers -------------------------------------------------
__device__ __forceinline__ void fma2(unsigned long long& d,
                                     unsigned long long a,
                                     unsigned long long b) {
    asm("fma.rn.f32x2 %0, %1, %2, %0;" : "+l"(d) : "l"(a), "l"(b));
}
__device__ __forceinline__ float2 upk(unsigned long long v) {
    float2 r; asm("mov.b64 {%0,%1}, %2;" : "=f"(r.x), "=f"(r.y) : "l"(v)); return r;
}

__device__ __forceinline__ int bucket_key(float4 xv) {
    int k0 = min((int)(xv.x * 16.0f), 15);
    int k1 = min((int)(xv.y * 16.0f), 15);
    int k2 = min((int)(xv.z * 16.0f), 15);
    int k3 = min((int)(xv.w * 16.0f), 15);
    return (((k0 * 16 + k1) * 16 + k2) * 16) + k3;
}

// ---------------------------------------------------------------------------
// Sort kernels: zero hist -> histogram -> exclusive scan -> scatter
// ---------------------------------------------------------------------------
__global__ void sort_zero() {
    int i = blockIdx.x * SBLK + threadIdx.x;
    if (i < NBINS) g_hist[i] = 0;
}

__global__ void sort_hist(const float4* __restrict__ x, int N) {
    int n = blockIdx.x * SBLK + threadIdx.x;
    if (n >= N) return;
    atomicAdd(&g_hist[bucket_key(__ldg(x + n))], 1);
}

__global__ void __launch_bounds__(1024, 1) sort_scan() {
    __shared__ int buf[1024];
    __shared__ int carry;
    const int tid = threadIdx.x;
    if (tid == 0) carry = 0;
    __syncthreads();
    #pragma unroll 1
    for (int base = 0; base < NBINS; base += 1024) {
        int v = g_hist[base + tid];
        buf[tid] = v;
        __syncthreads();
        #pragma unroll
        for (int off = 1; off < 1024; off <<= 1) {
            int t = (tid >= off) ? buf[tid - off] : 0;
            __syncthreads();
            buf[tid] += t;
            __syncthreads();
        }
        g_cursor[base + tid] = carry + buf[tid] - v;   // exclusive
        __syncthreads();
        if (tid == 1023) carry += buf[1023];
        __syncthreads();
    }
}

__global__ void sort_scatter(const float4* __restrict__ x, int N) {
    int n = blockIdx.x * SBLK + threadIdx.x;
    if (n >= N) return;
    float4 xv = __ldg(x + n);
    int pos = atomicAdd(&g_cursor[bucket_key(xv)], 1);
    g_perm[pos] = n;
    g_xs[pos] = xv;
}

// ---------------------------------------------------------------------------
// Kernel A: multi-res 4D hash encode in SORTED order, levels in pairs
// (l, l+8): 32 gathers in flight per thread, coarse+fine mixed per window.
// ---------------------------------------------------------------------------
__global__ void __launch_bounds__(EBLK, 3)
ingp_encode(const float2* __restrict__ table, int N, Res4 res)
{
    const int i = blockIdx.x * EBLK + threadIdx.x;
    if (i >= N) return;
    const float4 xv = __ldg(&g_xs[i]);

    #pragma unroll 1
    for (int lp = 0; lp < 8; lp++) {
        const int la = lp, lb = lp + 8;

        // ---- level A indices & weights ----
        float ra0 = (float)res.v[la][0] - 1.0f, ra1 = (float)res.v[la][1] - 1.0f;
        float ra2 = (float)res.v[la][2] - 1.0f, ra3 = (float)res.v[la][3] - 1.0f;
        float pa0 = xv.x * ra0, pa1 = xv.y * ra1, pa2 = xv.z * ra2, pa3 = xv.w * ra3;
        float ba0 = floorf(pa0), ba1 = floorf(pa1), ba2 = floorf(pa2), ba3 = floorf(pa3);
        float fa0 = pa0 - ba0, fa1 = pa1 - ba1, fa2 = pa2 - ba2, fa3 = pa3 - ba3;
        float ga0 = 1.f - fa0, ga1 = 1.f - fa1, ga2 = 1.f - fa2, ga3 = 1.f - fa3;
        unsigned Aa0 = (unsigned)(int)ba0;               unsigned Ab0 = Aa0 + 1u;
        unsigned Aa1 = (unsigned)(int)ba1 * 2654435761u; unsigned Ab1 = Aa1 + 2654435761u;
        unsigned Aa2 = (unsigned)(int)ba2 * 805459861u;  unsigned Ab2 = Aa2 + 805459861u;
        unsigned Aa3 = (unsigned)(int)ba3 * 3674653429u; unsigned Ab3 = Aa3 + 3674653429u;
        unsigned Axy[4] = { Aa0 ^ Aa1, Ab0 ^ Aa1, Aa0 ^ Ab1, Ab0 ^ Ab1 };
        unsigned Azw[4] = { Aa2 ^ Aa3, Ab2 ^ Aa3, Aa2 ^ Ab3, Ab2 ^ Ab3 };
        float    Wxy[4] = { ga0 * ga1, fa0 * ga1, ga0 * fa1, fa0 * fa1 };
        float    Wzw[4] = { ga2 * ga3, fa2 * ga3, ga2 * fa3, fa2 * fa3 };

        // ---- level B indices & weights ----
        float rb0 = (float)res.v[lb][0] - 1.0f, rb1 = (float)res.v[lb][1] - 1.0f;
        float rb2 = (float)res.v[lb][2] - 1.0f, rb3 = (float)res.v[lb][3] - 1.0f;
        float pb0 = xv.x * rb0, pb1 = xv.y * rb1, pb2 = xv.z * rb2, pb3 = xv.w * rb3;
        float bb0 = floorf(pb0), bb1 = floorf(pb1), bb2 = floorf(pb2), bb3 = floorf(pb3);
        float fb0 = pb0 - bb0, fb1 = pb1 - bb1, fb2 = pb2 - bb2, fb3 = pb3 - bb3;
        float gb0 = 1.f - fb0, gb1 = 1.f - fb1, gb2 = 1.f - fb2, gb3 = 1.f - fb3;
        unsigned Ba0 = (unsigned)(int)bb0;               unsigned Bb0 = Ba0 + 1u;
        unsigned Ba1 = (unsigned)(int)bb1 * 2654435761u; unsigned Bb1 = Ba1 + 2654435761u;
        unsigned Ba2 = (unsigned)(int)bb2 * 805459861u;  unsigned Bb2 = Ba2 + 805459861u;
        unsigned Ba3 = (unsigned)(int)bb3 * 3674653429u; unsigned Bb3 = Ba3 + 3674653429u;
        unsigned Bxy[4] = { Ba0 ^ Ba1, Bb0 ^ Ba1, Ba0 ^ Bb1, Bb0 ^ Bb1 };
        unsigned Bzw[4] = { Ba2 ^ Ba3, Bb2 ^ Ba3, Ba2 ^ Bb3, Bb2 ^ Bb3 };
        float    Vxy[4] = { gb0 * gb1, fb0 * gb1, gb0 * fb1, fb0 * fb1 };
        float    Vzw[4] = { gb2 * gb3, fb2 * gb3, gb2 * fb3, fb2 * fb3 };

        const float2* tA = table + ((size_t)la << 19);
        const float2* tB = table + ((size_t)lb << 19);
        float accA0 = 0.f, accA1 = 0.f, accB0 = 0.f, accB1 = 0.f;
        #pragma unroll
        for (int c = 0; c < 16; c++) {
            unsigned ia = (Axy[c & 3] ^ Azw[(c >> 2) & 3]) & (THASH - 1u);
            unsigned ib = (Bxy[c & 3] ^ Bzw[(c >> 2) & 3]) & (THASH - 1u);
            float2 va = __ldg(tA + ia);
            float2 vb = __ldg(tB + ib);
            float wa = Wxy[c & 3] * Wzw[(c >> 2) & 3];
            float wb = Vxy[c & 3] * Vzw[(c >> 2) & 3];
            accA0 = fmaf(wa, va.x, accA0);
            accA1 = fmaf(wa, va.y, accA1);
            accB0 = fmaf(wb, vb.x, accB0);
            accB1 = fmaf(wb, vb.y, accB1);
        }
        g_feat[la][i] = make_float2(accA0, accA1);
        g_feat[lb][i] = make_float2(accB0, accB1);
    }
}

// ---------------------------------------------------------------------------
// Kernel B: MLP (proven R5 form: 2 points/thread, FFMA2, smem weight
// broadcast). Reads features in sorted order, scatters outputs via perm.
// ---------------------------------------------------------------------------
__global__ void __launch_bounds__(MBLK, 2)
ingp_mlp(const float* __restrict__ w0,
         const float* __restrict__ w1,
         const float* __restrict__ w2,
         const float* __restrict__ w_out,
         const float* __restrict__ b_out,
         float* __restrict__ out, int N)
{
    extern __shared__ float sm[];
    float* s_w0 = sm;                       // [64][32]
    float* s_w1 = sm + 2048;                // [64][64]
    float* s_w2 = sm + 6144;                // [64][64]
    float* s_wo = sm + 10240;               // [3][64]
    float* s_bo = sm + 10432;               // 3 (+pad)
    float* s_actA = sm + WTOT;              // MBLK * ACT_STRIDE
    float* s_actB = s_actA + MBLK * ACT_STRIDE;

    const int tid = threadIdx.x;

    {   // cooperative weight load
        float4* dw0 = (float4*)s_w0; const float4* sw0 = (const float4*)w0;
        float4* dw1 = (float4*)s_w1; const float4* sw1 = (const float4*)w1;
        float4* dw2 = (float4*)s_w2; const float4* sw2 = (const float4*)w2;
        float4* dwo = (float4*)s_wo; const float4* swo = (const float4*)w_out;
        #pragma unroll 1
        for (int i = tid; i < 512;  i += MBLK) dw0[i] = sw0[i];
        #pragma unroll 1
        for (int i = tid; i < 1024; i += MBLK) dw1[i] = sw1[i];
        #pragma unroll 1
        for (int i = tid; i < 1024; i += MBLK) dw2[i] = sw2[i];
        if (tid < 48) dwo[tid] = swo[tid];
        if (tid < 3)  s_bo[tid] = b_out[tid];
    }
    __syncthreads();

    const int iA = blockIdx.x * (2 * MBLK) + tid;
    const int iB = iA + MBLK;
    if (iA >= N) return;
    const bool hasB = (iB < N);

    float* arowA = s_actA + tid * ACT_STRIDE;
    float* arowB = s_actB + tid * ACT_STRIDE;

    unsigned long long finA[32], finB[32];

    #pragma unroll
    for (int l = 0; l < NLEV; l++) {
        finA[l] = __ldg((const unsigned long long*)&g_feat[l][iA]);
        finB[l] = hasB ? __ldg((const unsigned long long*)&g_feat[l][iB]) : 0ull;
    }

    // ---- layer 0: 32 -> 64, ReLU ----
    #pragma unroll 1
    for (int j = 0; j < 64; j += 4) {
        unsigned long long a0 = 0, a1 = 0, a2 = 0, a3 = 0;
        unsigned long long c0 = 0, c1 = 0, c2 = 0, c3 = 0;
        const ulonglong2* r0 = (const ulonglong2*)(s_w0 + (j + 0) * 32);
        const ulonglong2* r1 = (const ulonglong2*)(s_w0 + (j + 1) * 32);
        const ulonglong2* r2 = (const ulonglong2*)(s_w0 + (j + 2) * 32);
        const ulonglong2* r3 = (const ulonglong2*)(s_w0 + (j + 3) * 32);
        #pragma unroll
        for (int q = 0; q < 8; q++) {
            unsigned long long pA0 = finA[2*q], pA1 = finA[2*q+1];
            unsigned long long pB0 = finB[2*q], pB1 = finB[2*q+1];
            ulonglong2 wa = r0[q];
            fma2(a0, pA0, wa.x); fma2(a0, pA1, wa.y);
            fma2(c0, pB0, wa.x); fma2(c0, pB1, wa.y);
            ulonglong2 wb = r1[q];
            fma2(a1, pA0, wb.x); fma2(a1, pA1, wb.y);
            fma2(c1, pB0, wb.x); fma2(c1, pB1, wb.y);
            ulonglong2 wc = r2[q];
            fma2(a2, pA0, wc.x); fma2(a2, pA1, wc.y);
            fma2(c2, pB0, wc.x); fma2(c2, pB1, wc.y);
            ulonglong2 wd = r3[q];
            fma2(a3, pA0, wd.x); fma2(a3, pA1, wd.y);
            fma2(c3, pB0, wd.x); fma2(c3, pB1, wd.y);
        }
        float2 s0 = upk(a0), s1 = upk(a1), s2 = upk(a2), s3 = upk(a3);
        float2 t0 = upk(c0), t1 = upk(c1), t2 = upk(c2), t3 = upk(c3);
        ((float4*)arowA)[j >> 2] = make_float4(fmaxf(s0.x + s0.y, 0.f),
                                               fmaxf(s1.x + s1.y, 0.f),
                                               fmaxf(s2.x + s2.y, 0.f),
                                               fmaxf(s3.x + s3.y, 0.f));
        ((float4*)arowB)[j >> 2] = make_float4(fmaxf(t0.x + t0.y, 0.f),
                                               fmaxf(t1.x + t1.y, 0.f),
                                               fmaxf(t2.x + t2.y, 0.f),
                                               fmaxf(t3.x + t3.y, 0.f));
    }

    // ---- layers 1 & 2: 64 -> 64, ReLU ----
    #pragma unroll 1
    for (int layer = 0; layer < 2; layer++) {
        const float* s_w = (layer == 0) ? s_w1 : s_w2;
        #pragma unroll
        for (int q = 0; q < 16; q++) {
            ulonglong2 vA = ((const ulonglong2*)arowA)[q];
            ulonglong2 vB = ((const ulonglong2*)arowB)[q];
            finA[2*q] = vA.x; finA[2*q+1] = vA.y;
            finB[2*q] = vB.x; finB[2*q+1] = vB.y;
        }
        #pragma unroll 1
        for (int j = 0; j < 64; j += 4) {
            unsigned long long a0 = 0, a1 = 0, a2 = 0, a3 = 0;
            unsigned long long c0 = 0, c1 = 0, c2 = 0, c3 = 0;
            const ulonglong2* r0 = (const ulonglong2*)(s_w + (j + 0) * 64);
            const ulonglong2* r1 = (const ulonglong2*)(s_w + (j + 1) * 64);
            const ulonglong2* r2 = (const ulonglong2*)(s_w + (j + 2) * 64);
            const ulonglong2* r3 = (const ulonglong2*)(s_w + (j + 3) * 64);
            #pragma unroll
            for (int q = 0; q < 16; q++) {
                unsigned long long pA0 = finA[2*q], pA1 = finA[2*q+1];
                unsigned long long pB0 = finB[2*q], pB1 = finB[2*q+1];
                ulonglong2 wa = r0[q];
                fma2(a0, pA0, wa.x); fma2(a0, pA1, wa.y);
                fma2(c0, pB0, wa.x); fma2(c0, pB1, wa.y);
                ulonglong2 wb = r1[q];
                fma2(a1, pA0, wb.x); fma2(a1, pA1, wb.y);
                fma2(c1, pB0, wb.x); fma2(c1, pB1, wb.y);
                ulonglong2 wc = r2[q];
                fma2(a2, pA0, wc.x); fma2(a2, pA1, wc.y);
                fma2(c2, pB0, wc.x); fma2(c2, pB1, wc.y);
                ulonglong2 wd = r3[q];
                fma2(a3, pA0, wd.x); fma2(a3, pA1, wd.y);
                fma2(c3, pB0, wd.x); fma2(c3, pB1, wd.y);
            }
            float2 s0 = upk(a0), s1 = upk(a1), s2 = upk(a2), s3 = upk(a3);
            float2 t0 = upk(c0), t1 = upk(c1), t2 = upk(c2), t3 = upk(c3);
            ((float4*)arowA)[j >> 2] = make_float4(fmaxf(s0.x + s0.y, 0.f),
                                                   fmaxf(s1.x + s1.y, 0.f),
                                                   fmaxf(s2.x + s2.y, 0.f),
                                                   fmaxf(s3.x + s3.y, 0.f));
            ((float4*)arowB)[j >> 2] = make_float4(fmaxf(t0.x + t0.y, 0.f),
                                                   fmaxf(t1.x + t1.y, 0.f),
                                                   fmaxf(t2.x + t2.y, 0.f),
                                                   fmaxf(t3.x + t3.y, 0.f));
        }
    }

    // ---- output layer: 64 -> 3, + bias ----
    #pragma unroll
    for (int q = 0; q < 16; q++) {
        ulonglong2 vA = ((const ulonglong2*)arowA)[q];
        ulonglong2 vB = ((const ulonglong2*)arowB)[q];
        finA[2*q] = vA.x; finA[2*q+1] = vA.y;
        finB[2*q] = vB.x; finB[2*q+1] = vB.y;
    }
    {
        unsigned long long a0 = 0, a1 = 0, a2 = 0;
        unsigned long long c0 = 0, c1 = 0, c2 = 0;
        const ulonglong2* r0 = (const ulonglong2*)(s_wo + 0);
        const ulonglong2* r1 = (const ulonglong2*)(s_wo + 64);
        const ulonglong2* r2 = (const ulonglong2*)(s_wo + 128);
        #pragma unroll
        for (int q = 0; q < 16; q++) {
            unsigned long long pA0 = finA[2*q], pA1 = finA[2*q+1];
            unsigned long long pB0 = finB[2*q], pB1 = finB[2*q+1];
            ulonglong2 wa = r0[q];
            fma2(a0, pA0, wa.x); fma2(a0, pA1, wa.y);
            fma2(c0, pB0, wa.x); fma2(c0, pB1, wa.y);
            ulonglong2 wb = r1[q];
            fma2(a1, pA0, wb.x); fma2(a1, pA1, wb.y);
            fma2(c1, pB0, wb.x); fma2(c1, pB1, wb.y);
            ulonglong2 wc = r2[q];
            fma2(a2, pA0, wc.x); fma2(a2, pA1, wc.y);
            fma2(c2, pB0, wc.x); fma2(c2, pB1, wc.y);
        }
        float2 s0 = upk(a0), s1 = upk(a1), s2 = upk(a2);
        float2 t0 = upk(c0), t1 = upk(c1), t2 = upk(c2);
        const float bo0 = s_bo[0], bo1 = s_bo[1], bo2 = s_bo[2];
        const int nA = __ldg(&g_perm[iA]);
        size_t obA = (size_t)nA * 3;
        out[obA + 0] = bo0 + s0.x + s0.y;
        out[obA + 1] = bo1 + s1.x + s1.y;
        out[obA + 2] = bo2 + s2.x + s2.y;
        if (hasB) {
            const int nB = __ldg(&g_perm[iB]);
            size_t obB = (size_t)nB * 3;
            out[obB + 0] = bo0 + t0.x + t0.y;
            out[obB + 1] = bo1 + t1.x + t1.y;
            out[obB + 2] = bo2 + t2.x + t2.y;
        }
    }
}

extern "C" void kernel_launch(void* const* d_in, const int* in_sizes, int n_in,
                              void* d_out, int out_size)
{
    const float4* x     = (const float4*)d_in[0];
    const float2* table = (const float2*)d_in[1];
    const float*  w0    = (const float*)d_in[2];
    const float*  w1    = (const float*)d_in[3];
    const float*  w2    = (const float*)d_in[4];
    const float*  w_out = (const float*)d_in[5];
    const float*  b_out = (const float*)d_in[6];
    float* out = (float*)d_out;
    const int N = in_sizes[0] / 4;

    // Replicate numpy's RES computation bit-exactly (same aarch64 glibc pow/floor).
    Res4 res;
    const double minr[4] = {16.0, 16.0, 16.0, 16.0};
    const double maxr[4] = {256.0, 256.0, 256.0, 128.0};
    for (int d = 0; d < 4; d++) {
        double g = pow(maxr[d] / minr[d], 1.0 / 15.0);
        for (int l = 0; l < NLEV; l++) {
            res.v[l][d] = (int)floor(minr[d] * pow(g, (double)l));
        }
    }

    size_t smem = (size_t)(WTOT + 2 * MBLK * ACT_STRIDE) * sizeof(float);
    cudaFuncSetAttribute(ingp_mlp, cudaFuncAttributeMaxDynamicSharedMemorySize, (int)smem);

    const int pgrid = (N + SBLK - 1) / SBLK;

    // spatial counting sort: hist -> scan -> scatter (perm + sorted x)
    sort_zero<<<(NBINS + SBLK - 1) / SBLK, SBLK>>>();
    sort_hist<<<pgrid, SBLK>>>(x, N);
    sort_scan<<<1, 1024>>>();
    sort_scatter<<<pgrid, SBLK>>>(x, N);

    int egrid = (N + EBLK - 1) / EBLK;
    ingp_encode<<<egrid, EBLK>>>(table, N, res);
    int mgrid = (N + 2 * MBLK - 1) / (2 * MBLK);
    ingp_mlp<<<mgrid, MBLK, smem>>>(w0, w1, w2, w_out, b_out, out, N);
}

// round 11
// speedup vs baseline: 1.6193x; 1.6193x over previous
#include <cuda_runtime.h>
#include <cuda_bf16.h>
#include <math.h>
#include <stdint.h>

#define NLEV 16
#define THASH (1u << 19)
#define EBLK 256
#define NMAX (1 << 20)
#define NBINS 65536
#define SBLK 256

struct Res4 { int v[NLEV][4]; };

// Feature scratch (sorted order), level-major.
__device__ float2 g_feat[NLEV][NMAX];
__device__ float4 g_xs[NMAX];
__device__ int g_perm[NMAX];
__device__ int g_hist[NBINS];
__device__ int g_cursor[NBINS];
// B fragments (m16n8k16 col-major) per layer: [ktile*8+ntile][lane] as 8B (b0|b1).
__device__ unsigned long long g_w0f[16 * 32];   // K=32: 2 ktiles x 8 ntiles
__device__ unsigned long long g_w1f[32 * 32];   // K=64: 4 ktiles x 8 ntiles
__device__ unsigned long long g_w2f[32 * 32];

// ---- helpers ----------------------------------------------------------------
__device__ __forceinline__ uint32_t pack_bf16x2(float lo, float hi) {
    uint32_t r;
    asm("cvt.rn.bf16x2.f32 %0, %1, %2;" : "=r"(r) : "f"(hi), "f"(lo));
    return r;
}
__device__ __forceinline__ void mma16816(float* d, const uint32_t* a, uint32_t b0, uint32_t b1) {
    asm volatile("mma.sync.aligned.m16n8k16.row.col.f32.bf16.bf16.f32 "
                 "{%0,%1,%2,%3}, {%4,%5,%6,%7}, {%8,%9}, {%0,%1,%2,%3};"
                 : "+f"(d[0]), "+f"(d[1]), "+f"(d[2]), "+f"(d[3])
                 : "r"(a[0]), "r"(a[1]), "r"(a[2]), "r"(a[3]), "r"(b0), "r"(b1));
}

// ---------------------------------------------------------------------------
// Sort kernels
// ---------------------------------------------------------------------------
__device__ __forceinline__ int bucket_key(float4 xv) {
    int k0 = min((int)(xv.x * 16.0f), 15);
    int k1 = min((int)(xv.y * 16.0f), 15);
    int k2 = min((int)(xv.z * 16.0f), 15);
    int k3 = min((int)(xv.w * 16.0f), 15);
    return (((k0 * 16 + k1) * 16 + k2) * 16) + k3;
}

__global__ void sort_zero() {
    int i = blockIdx.x * SBLK + threadIdx.x;
    if (i < NBINS) g_hist[i] = 0;
}
__global__ void sort_hist(const float4* __restrict__ x, int N) {
    int n = blockIdx.x * SBLK + threadIdx.x;
    if (n >= N) return;
    atomicAdd(&g_hist[bucket_key(__ldg(x + n))], 1);
}
__global__ void __launch_bounds__(1024, 1) sort_scan() {
    __shared__ int buf[1024];
    __shared__ int carry;
    const int tid = threadIdx.x;
    if (tid == 0) carry = 0;
    __syncthreads();
    #pragma unroll 1
    for (int base = 0; base < NBINS; base += 1024) {
        int v = g_hist[base + tid];
        buf[tid] = v;
        __syncthreads();
        #pragma unroll
        for (int off = 1; off < 1024; off <<= 1) {
            int t = (tid >= off) ? buf[tid - off] : 0;
            __syncthreads();
            buf[tid] += t;
            __syncthreads();
        }
        g_cursor[base + tid] = carry + buf[tid] - v;
        __syncthreads();
        if (tid == 1023) carry += buf[1023];
        __syncthreads();
    }
}
__global__ void sort_scatter(const float4* __restrict__ x, int N) {
    int n = blockIdx.x * SBLK + threadIdx.x;
    if (n >= N) return;
    float4 xv = __ldg(x + n);
    int pos = atomicAdd(&g_cursor[bucket_key(xv)], 1);
    g_perm[pos] = n;
    g_xs[pos] = xv;
}

// ---------------------------------------------------------------------------
// Weight prep: fp32 [64][K] -> bf16 B fragments (m16n8k16 col-major).
// frag[kt*8+nt][lane]: n = nt*8 + lane/4, kbase = kt*16 + (lane%4)*2
//   b0 = {W[n][kbase], W[n][kbase+1]}, b1 = {W[n][kbase+8], W[n][kbase+9]}
// ---------------------------------------------------------------------------
__global__ void __launch_bounds__(256) prep_weights(const float* __restrict__ w0,
                                                    const float* __restrict__ w1,
                                                    const float* __restrict__ w2)
{
    const int tid = threadIdx.x;
    // W0: K=32, 16 fragments
    for (int idx = tid; idx < 16 * 32; idx += 256) {
        int frag = idx >> 5, lane = idx & 31;
        int kt = frag >> 3, nt = frag & 7;
        int n = nt * 8 + (lane >> 2);
        int kb = kt * 16 + (lane & 3) * 2;
        uint32_t b0 = pack_bf16x2(w0[n * 32 + kb],     w0[n * 32 + kb + 1]);
        uint32_t b1 = pack_bf16x2(w0[n * 32 + kb + 8], w0[n * 32 + kb + 9]);
        g_w0f[idx] = (unsigned long long)b0 | ((unsigned long long)b1 << 32);
    }
    // W1/W2: K=64, 32 fragments
    for (int idx = tid; idx < 32 * 32; idx += 256) {
        int frag = idx >> 5, lane = idx & 31;
        int kt = frag >> 3, nt = frag & 7;
        int n = nt * 8 + (lane >> 2);
        int kb = kt * 16 + (lane & 3) * 2;
        uint32_t b0 = pack_bf16x2(w1[n * 64 + kb],     w1[n * 64 + kb + 1]);
        uint32_t b1 = pack_bf16x2(w1[n * 64 + kb + 8], w1[n * 64 + kb + 9]);
        g_w1f[idx] = (unsigned long long)b0 | ((unsigned long long)b1 << 32);
        b0 = pack_bf16x2(w2[n * 64 + kb],     w2[n * 64 + kb + 1]);
        b1 = pack_bf16x2(w2[n * 64 + kb + 8], w2[n * 64 + kb + 9]);
        g_w2f[idx] = (unsigned long long)b0 | ((unsigned long long)b1 << 32);
    }
}

// ---------------------------------------------------------------------------
// Kernel A: multi-res 4D hash encode (proven R8 loop, coalesced sorted x).
// ---------------------------------------------------------------------------
__global__ void __launch_bounds__(EBLK, 4)
ingp_encode(const float2* __restrict__ table, int N, Res4 res)
{
    const int i = blockIdx.x * EBLK + threadIdx.x;
    if (i >= N) return;
    const float4 xv = __ldg(&g_xs[i]);

    #pragma unroll 1
    for (int l = 0; l < NLEV; l++) {
        const float r0 = (float)res.v[l][0] - 1.0f;
        const float r1 = (float)res.v[l][1] - 1.0f;
        const float r2 = (float)res.v[l][2] - 1.0f;
        const float r3 = (float)res.v[l][3] - 1.0f;
        float p0 = xv.x * r0, p1 = xv.y * r1, p2 = xv.z * r2, p3 = xv.w * r3;
        float b0 = floorf(p0), b1 = floorf(p1), b2 = floorf(p2), b3 = floorf(p3);
        float f0 = p0 - b0, f1 = p1 - b1, f2 = p2 - b2, f3 = p3 - b3;
        float g0 = 1.f - f0, g1 = 1.f - f1, g2 = 1.f - f2, g3 = 1.f - f3;

        unsigned ha0 = (unsigned)(int)b0;                 unsigned hb0 = ha0 + 1u;
        unsigned ha1 = (unsigned)(int)b1 * 2654435761u;   unsigned hb1 = ha1 + 2654435761u;
        unsigned ha2 = (unsigned)(int)b2 * 805459861u;    unsigned hb2 = ha2 + 805459861u;
        unsigned ha3 = (unsigned)(int)b3 * 3674653429u;   unsigned hb3 = ha3 + 3674653429u;

        unsigned hxy[4] = { ha0 ^ ha1, hb0 ^ ha1, ha0 ^ hb1, hb0 ^ hb1 };
        unsigned hzw[4] = { ha2 ^ ha3, hb2 ^ ha3, ha2 ^ hb3, hb2 ^ hb3 };
        float    wxy[4] = { g0 * g1,  f0 * g1,  g0 * f1,  f0 * f1 };
        float    wzw[4] = { g2 * g3,  f2 * g3,  g2 * f3,  f2 * f3 };

        const float2* tl = table + ((size_t)l << 19);
        float acc0 = 0.f, acc1 = 0.f;
        #pragma unroll
        for (int c = 0; c < 16; c++) {
            unsigned idx = (hxy[c & 3] ^ hzw[(c >> 2) & 3]) & (THASH - 1u);
            float2 t2 = __ldg(tl + idx);
            float w = wxy[c & 3] * wzw[(c >> 2) & 3];
            acc0 = fmaf(w, t2.x, acc0);
            acc1 = fmaf(w, t2.y, acc1);
        }
        g_feat[l][i] = make_float2(acc0, acc1);
    }
}

// ---------------------------------------------------------------------------
// Kernel B: HMMA (mma.sync m16n8k16 bf16) MLP. 8 warps/CTA, 16 points/warp.
// Layers chain D->A entirely in registers (fragment layouts compose).
// ---------------------------------------------------------------------------
__global__ void __launch_bounds__(256)
ingp_mlp_mma(const float* __restrict__ w_out, const float* __restrict__ b_out,
             float* __restrict__ out, int N)
{
    __shared__ unsigned long long s_w0f[16 * 32];
    __shared__ unsigned long long s_w1f[32 * 32];
    __shared__ unsigned long long s_w2f[32 * 32];
    __shared__ float s_wo[192];
    __shared__ float s_bo[4];

    const int tid = threadIdx.x;
    const int wid = tid >> 5;
    const int lane = tid & 31;

    for (int i = tid; i < 16 * 32; i += 256) s_w0f[i] = g_w0f[i];
    for (int i = tid; i < 32 * 32; i += 256) { s_w1f[i] = g_w1f[i]; s_w2f[i] = g_w2f[i]; }
    if (tid < 192) s_wo[tid] = w_out[tid];
    if (tid < 3)   s_bo[tid] = b_out[tid];
    __syncthreads();

    const int m0 = blockIdx.x * 128 + wid * 16;     // warp's 16-point tile
    const int r = lane >> 2;                        // fragment row
    const int q = lane & 3;                         // k-quad
    const int p0 = m0 + r;
    const int p1 = m0 + r + 8;
    const bool v0 = (p0 < N), v1 = (p1 < N);
    const int i0 = v0 ? p0 : 0;
    const int i1 = v1 ? p1 : 0;

    float d[8][4];                                   // D: 8 n-tiles x 4 f32
    uint32_t a[4][4];                                // A: up to 4 k-tiles x 4 b32

    // ---- layer 0: A from features (K=32 -> 2 k-tiles) ----
    #pragma unroll
    for (int kt = 0; kt < 2; kt++) {
        int lv0 = kt * 8 + q;                        // k=(q*2) -> level q (+8 per ktile)
        int lv1 = lv0 + 4;                           // k+8 -> level +4
        float2 f00 = __ldg(&g_feat[lv0][i0]);
        float2 f01 = __ldg(&g_feat[lv0][i1]);
        float2 f10 = __ldg(&g_feat[lv1][i0]);
        float2 f11 = __ldg(&g_feat[lv1][i1]);
        a[kt][0] = pack_bf16x2(f00.x, f00.y);
        a[kt][1] = pack_bf16x2(f01.x, f01.y);
        a[kt][2] = pack_bf16x2(f10.x, f10.y);
        a[kt][3] = pack_bf16x2(f11.x, f11.y);
    }
    #pragma unroll
    for (int nt = 0; nt < 8; nt++) {
        d[nt][0] = d[nt][1] = d[nt][2] = d[nt][3] = 0.f;
        #pragma unroll
        for (int kt = 0; kt < 2; kt++) {
            unsigned long long w = s_w0f[(kt * 8 + nt) * 32 + lane];
            mma16816(d[nt], a[kt], (uint32_t)w, (uint32_t)(w >> 32));
        }
    }

    // ---- layers 1 & 2: relu(D) -> A (register-only), then 4x8 MMAs ----
    #pragma unroll
    for (int layer = 0; layer < 2; layer++) {
        const unsigned long long* s_wf = (layer == 0) ? s_w1f : s_w2f;
        #pragma unroll
        for (int kt = 0; kt < 4; kt++) {
            a[kt][0] = pack_bf16x2(fmaxf(d[2*kt][0], 0.f),   fmaxf(d[2*kt][1], 0.f));
            a[kt][1] = pack_bf16x2(fmaxf(d[2*kt][2], 0.f),   fmaxf(d[2*kt][3], 0.f));
            a[kt][2] = pack_bf16x2(fmaxf(d[2*kt+1][0], 0.f), fmaxf(d[2*kt+1][1], 0.f));
            a[kt][3] = pack_bf16x2(fmaxf(d[2*kt+1][2], 0.f), fmaxf(d[2*kt+1][3], 0.f));
        }
        #pragma unroll
        for (int nt = 0; nt < 8; nt++) {
            d[nt][0] = d[nt][1] = d[nt][2] = d[nt][3] = 0.f;
            #pragma unroll
            for (int kt = 0; kt < 4; kt++) {
                unsigned long long w = s_wf[(kt * 8 + nt) * 32 + lane];
                mma16816(d[nt], a[kt], (uint32_t)w, (uint32_t)(w >> 32));
            }
        }
    }

    // ---- final: out = relu(D) @ Wout^T + b, quad-reduced ----
    {
        float o00 = 0.f, o01 = 0.f, o02 = 0.f;   // row r
        float o10 = 0.f, o11 = 0.f, o12 = 0.f;   // row r+8
        #pragma unroll
        for (int nt = 0; nt < 8; nt++) {
            int c = nt * 8 + q * 2;
            float h00 = fmaxf(d[nt][0], 0.f), h01 = fmaxf(d[nt][1], 0.f);
            float h10 = fmaxf(d[nt][2], 0.f), h11 = fmaxf(d[nt][3], 0.f);
            float wa0 = s_wo[c],       wb0 = s_wo[c + 1];
            float wa1 = s_wo[64 + c],  wb1 = s_wo[64 + c + 1];
            float wa2 = s_wo[128 + c], wb2 = s_wo[128 + c + 1];
            o00 = fmaf(h00, wa0, fmaf(h01, wb0, o00));
            o01 = fmaf(h00, wa1, fmaf(h01, wb1, o01));
            o02 = fmaf(h00, wa2, fmaf(h01, wb2, o02));
            o10 = fmaf(h10, wa0, fmaf(h11, wb0, o10));
            o11 = fmaf(h10, wa1, fmaf(h11, wb1, o11));
            o12 = fmaf(h10, wa2, fmaf(h11, wb2, o12));
        }
        #pragma unroll
        for (int off = 1; off <= 2; off <<= 1) {
            o00 += __shfl_xor_sync(0xFFFFFFFF, o00, off);
            o01 += __shfl_xor_sync(0xFFFFFFFF, o01, off);
            o02 += __shfl_xor_sync(0xFFFFFFFF, o02, off);
            o10 += __shfl_xor_sync(0xFFFFFFFF, o10, off);
            o11 += __shfl_xor_sync(0xFFFFFFFF, o11, off);
            o12 += __shfl_xor_sync(0xFFFFFFFF, o12, off);
        }
        if (q == 0) {
            const float b0 = s_bo[0], b1 = s_bo[1], b2 = s_bo[2];
            if (v0) {
                size_t ob = (size_t)__ldg(&g_perm[p0]) * 3;
                out[ob + 0] = b0 + o00;
                out[ob + 1] = b1 + o01;
                out[ob + 2] = b2 + o02;
            }
            if (v1) {
                size_t ob = (size_t)__ldg(&g_perm[p1]) * 3;
                out[ob + 0] = b0 + o10;
                out[ob + 1] = b1 + o11;
                out[ob + 2] = b2 + o12;
            }
        }
    }
}

extern "C" void kernel_launch(void* const* d_in, const int* in_sizes, int n_in,
                              void* d_out, int out_size)
{
    const float4* x     = (const float4*)d_in[0];
    const float2* table = (const float2*)d_in[1];
    const float*  w0    = (const float*)d_in[2];
    const float*  w1    = (const float*)d_in[3];
    const float*  w2    = (const float*)d_in[4];
    const float*  w_out = (const float*)d_in[5];
    const float*  b_out = (const float*)d_in[6];
    float* out = (float*)d_out;
    const int N = in_sizes[0] / 4;

    // Replicate numpy's RES computation bit-exactly (same aarch64 glibc pow/floor).
    Res4 res;
    const double minr[4] = {16.0, 16.0, 16.0, 16.0};
    const double maxr[4] = {256.0, 256.0, 256.0, 128.0};
    for (int d = 0; d < 4; d++) {
        double g = pow(maxr[d] / minr[d], 1.0 / 15.0);
        for (int l = 0; l < NLEV; l++) {
            res.v[l][d] = (int)floor(minr[d] * pow(g, (double)l));
        }
    }

    const int pgrid = (N + SBLK - 1) / SBLK;

    prep_weights<<<1, 256>>>(w0, w1, w2);
    sort_zero<<<(NBINS + SBLK - 1) / SBLK, SBLK>>>();
    sort_hist<<<pgrid, SBLK>>>(x, N);
    sort_scan<<<1, 1024>>>();
    sort_scatter<<<pgrid, SBLK>>>(x, N);

    int egrid = (N + EBLK - 1) / EBLK;
    ingp_encode<<<egrid, EBLK>>>(table, N, res);

    int mgrid = (N + 127) / 128;
    ingp_mlp_mma<<<mgrid, 256>>>(w_out, b_out, out, N);
}

// round 12
// speedup vs baseline: 1.8595x; 1.1483x over previous
#include <cuda_runtime.h>
#include <cuda_bf16.h>
#include <math.h>
#include <stdint.h>

#define NLEV 16
#define THASH (1u << 19)
#define EBLK 256
#define NMAX (1 << 20)
#define NBINS 65536
#define SBLK 256
#define NSEG 64            // scan segments (NBINS / 1024)

struct Res4 { int v[NLEV][4]; };

// Feature scratch (sorted order), level-major.
__device__ float2 g_feat[NLEV][NMAX];
__device__ float4 g_xs[NMAX];
__device__ int g_perm[NMAX];
__device__ int g_hist[NBINS];
__device__ int g_cursor[NBINS];
__device__ int g_segsum[NSEG];
// B fragments (m16n8k16 col-major) per layer: [ktile*8+ntile][lane] as 8B (b0|b1).
__device__ unsigned long long g_w0f[16 * 32];   // K=32: 2 ktiles x 8 ntiles
__device__ unsigned long long g_w1f[32 * 32];   // K=64: 4 ktiles x 8 ntiles
__device__ unsigned long long g_w2f[32 * 32];

// ---- helpers ----------------------------------------------------------------
__device__ __forceinline__ uint32_t pack_bf16x2(float lo, float hi) {
    uint32_t r;
    asm("cvt.rn.bf16x2.f32 %0, %1, %2;" : "=r"(r) : "f"(hi), "f"(lo));
    return r;
}
__device__ __forceinline__ void mma16816(float* d, const uint32_t* a, uint32_t b0, uint32_t b1) {
    asm volatile("mma.sync.aligned.m16n8k16.row.col.f32.bf16.bf16.f32 "
                 "{%0,%1,%2,%3}, {%4,%5,%6,%7}, {%8,%9}, {%0,%1,%2,%3};"
                 : "+f"(d[0]), "+f"(d[1]), "+f"(d[2]), "+f"(d[3])
                 : "r"(a[0]), "r"(a[1]), "r"(a[2]), "r"(a[3]), "r"(b0), "r"(b1));
}

// ---------------------------------------------------------------------------
// Sort kernels
// ---------------------------------------------------------------------------
__device__ __forceinline__ int bucket_key(float4 xv) {
    int k0 = min((int)(xv.x * 16.0f), 15);
    int k1 = min((int)(xv.y * 16.0f), 15);
    int k2 = min((int)(xv.z * 16.0f), 15);
    int k3 = min((int)(xv.w * 16.0f), 15);
    return (((k0 * 16 + k1) * 16 + k2) * 16) + k3;
}

__global__ void sort_zero() {
    int i = blockIdx.x * SBLK + threadIdx.x;
    if (i < NBINS) g_hist[i] = 0;
}
__global__ void sort_hist(const float4* __restrict__ x, int N) {
    int n = blockIdx.x * SBLK + threadIdx.x;
    if (n >= N) return;
    atomicAdd(&g_hist[bucket_key(__ldg(x + n))], 1);
}

// Stage 1: each CTA scans its 1024-bin segment (local exclusive), records total.
__global__ void __launch_bounds__(1024, 1) scan_stage1() {
    __shared__ int buf[1024];
    const int tid = threadIdx.x;
    const int base = blockIdx.x * 1024;
    int v = g_hist[base + tid];
    buf[tid] = v;
    __syncthreads();
    #pragma unroll
    for (int off = 1; off < 1024; off <<= 1) {
        int t = (tid >= off) ? buf[tid - off] : 0;
        __syncthreads();
        buf[tid] += t;
        __syncthreads();
    }
    g_cursor[base + tid] = buf[tid] - v;          // local exclusive
    if (tid == 1023) g_segsum[blockIdx.x] = buf[1023];
}

// Stage 2: exclusive scan of the 64 segment totals (one warp pair).
__global__ void __launch_bounds__(64, 1) scan_stage2() {
    __shared__ int buf[NSEG];
    const int tid = threadIdx.x;
    int v = g_segsum[tid];
    buf[tid] = v;
    __syncthreads();
    #pragma unroll
    for (int off = 1; off < NSEG; off <<= 1) {
        int t = (tid >= off) ? buf[tid - off] : 0;
        __syncthreads();
        buf[tid] += t;
        __syncthreads();
    }
    g_segsum[tid] = buf[tid] - v;                 // exclusive
}

// Stage 3: add segment offsets.
__global__ void __launch_bounds__(1024, 1) scan_stage3() {
    const int base = blockIdx.x * 1024;
    g_cursor[base + threadIdx.x] += g_segsum[blockIdx.x];
}

__global__ void sort_scatter(const float4* __restrict__ x, int N) {
    int n = blockIdx.x * SBLK + threadIdx.x;
    if (n >= N) return;
    float4 xv = __ldg(x + n);
    int pos = atomicAdd(&g_cursor[bucket_key(xv)], 1);
    g_perm[pos] = n;
    g_xs[pos] = xv;
}

// ---------------------------------------------------------------------------
// Weight prep: fp32 [64][K] -> bf16 B fragments (m16n8k16 col-major).
// ---------------------------------------------------------------------------
__global__ void __launch_bounds__(256) prep_weights(const float* __restrict__ w0,
                                                    const float* __restrict__ w1,
                                                    const float* __restrict__ w2)
{
    const int tid = threadIdx.x;
    for (int idx = tid; idx < 16 * 32; idx += 256) {
        int frag = idx >> 5, lane = idx & 31;
        int kt = frag >> 3, nt = frag & 7;
        int n = nt * 8 + (lane >> 2);
        int kb = kt * 16 + (lane & 3) * 2;
        uint32_t b0 = pack_bf16x2(w0[n * 32 + kb],     w0[n * 32 + kb + 1]);
        uint32_t b1 = pack_bf16x2(w0[n * 32 + kb + 8], w0[n * 32 + kb + 9]);
        g_w0f[idx] = (unsigned long long)b0 | ((unsigned long long)b1 << 32);
    }
    for (int idx = tid; idx < 32 * 32; idx += 256) {
        int frag = idx >> 5, lane = idx & 31;
        int kt = frag >> 3, nt = frag & 7;
        int n = nt * 8 + (lane >> 2);
        int kb = kt * 16 + (lane & 3) * 2;
        uint32_t b0 = pack_bf16x2(w1[n * 64 + kb],     w1[n * 64 + kb + 1]);
        uint32_t b1 = pack_bf16x2(w1[n * 64 + kb + 8], w1[n * 64 + kb + 9]);
        g_w1f[idx] = (unsigned long long)b0 | ((unsigned long long)b1 << 32);
        b0 = pack_bf16x2(w2[n * 64 + kb],     w2[n * 64 + kb + 1]);
        b1 = pack_bf16x2(w2[n * 64 + kb + 8], w2[n * 64 + kb + 9]);
        g_w2f[idx] = (unsigned long long)b0 | ((unsigned long long)b1 << 32);
    }
}

// ---------------------------------------------------------------------------
// Kernel A: multi-res 4D hash encode (proven R8 loop, coalesced sorted x).
// ---------------------------------------------------------------------------
__global__ void __launch_bounds__(EBLK, 4)
ingp_encode(const float2* __restrict__ table, int N, Res4 res)
{
    const int i = blockIdx.x * EBLK + threadIdx.x;
    if (i >= N) return;
    const float4 xv = __ldg(&g_xs[i]);

    #pragma unroll 1
    for (int l = 0; l < NLEV; l++) {
        const float r0 = (float)res.v[l][0] - 1.0f;
        const float r1 = (float)res.v[l][1] - 1.0f;
        const float r2 = (float)res.v[l][2] - 1.0f;
        const float r3 = (float)res.v[l][3] - 1.0f;
        float p0 = xv.x * r0, p1 = xv.y * r1, p2 = xv.z * r2, p3 = xv.w * r3;
        float b0 = floorf(p0), b1 = floorf(p1), b2 = floorf(p2), b3 = floorf(p3);
        float f0 = p0 - b0, f1 = p1 - b1, f2 = p2 - b2, f3 = p3 - b3;
        float g0 = 1.f - f0, g1 = 1.f - f1, g2 = 1.f - f2, g3 = 1.f - f3;

        unsigned ha0 = (unsigned)(int)b0;                 unsigned hb0 = ha0 + 1u;
        unsigned ha1 = (unsigned)(int)b1 * 2654435761u;   unsigned hb1 = ha1 + 2654435761u;
        unsigned ha2 = (unsigned)(int)b2 * 805459861u;    unsigned hb2 = ha2 + 805459861u;
        unsigned ha3 = (unsigned)(int)b3 * 3674653429u;   unsigned hb3 = ha3 + 3674653429u;

        unsigned hxy[4] = { ha0 ^ ha1, hb0 ^ ha1, ha0 ^ hb1, hb0 ^ hb1 };
        unsigned hzw[4] = { ha2 ^ ha3, hb2 ^ ha3, ha2 ^ hb3, hb2 ^ hb3 };
        float    wxy[4] = { g0 * g1,  f0 * g1,  g0 * f1,  f0 * f1 };
        float    wzw[4] = { g2 * g3,  f2 * g3,  g2 * f3,  f2 * f3 };

        const float2* tl = table + ((size_t)l << 19);
        float acc0 = 0.f, acc1 = 0.f;
        #pragma unroll
        for (int c = 0; c < 16; c++) {
            unsigned idx = (hxy[c & 3] ^ hzw[(c >> 2) & 3]) & (THASH - 1u);
            float2 t2 = __ldg(tl + idx);
            float w = wxy[c & 3] * wzw[(c >> 2) & 3];
            acc0 = fmaf(w, t2.x, acc0);
            acc1 = fmaf(w, t2.y, acc1);
        }
        g_feat[l][i] = make_float2(acc0, acc1);
    }
}

// ---------------------------------------------------------------------------
// Kernel B: HMMA (mma.sync m16n8k16 bf16) MLP. 8 warps/CTA, 16 points/warp.
// Layers chain D->A entirely in registers (fragment layouts compose).
// ---------------------------------------------------------------------------
__global__ void __launch_bounds__(256)
ingp_mlp_mma(const float* __restrict__ w_out, const float* __restrict__ b_out,
             float* __restrict__ out, int N)
{
    __shared__ unsigned long long s_w0f[16 * 32];
    __shared__ unsigned long long s_w1f[32 * 32];
    __shared__ unsigned long long s_w2f[32 * 32];
    __shared__ float s_wo[192];
    __shared__ float s_bo[4];

    const int tid = threadIdx.x;
    const int wid = tid >> 5;
    const int lane = tid & 31;

    for (int i = tid; i < 16 * 32; i += 256) s_w0f[i] = g_w0f[i];
    for (int i = tid; i < 32 * 32; i += 256) { s_w1f[i] = g_w1f[i]; s_w2f[i] = g_w2f[i]; }
    if (tid < 192) s_wo[tid] = w_out[tid];
    if (tid < 3)   s_bo[tid] = b_out[tid];
    __syncthreads();

    const int m0 = blockIdx.x * 128 + wid * 16;
    const int r = lane >> 2;
    const int q = lane & 3;
    const int p0 = m0 + r;
    const int p1 = m0 + r + 8;
    const bool v0 = (p0 < N), v1 = (p1 < N);
    const int i0 = v0 ? p0 : 0;
    const int i1 = v1 ? p1 : 0;

    float d[8][4];
    uint32_t a[4][4];

    // ---- layer 0 ----
    #pragma unroll
    for (int kt = 0; kt < 2; kt++) {
        int lv0 = kt * 8 + q;
        int lv1 = lv0 + 4;
        float2 f00 = __ldg(&g_feat[lv0][i0]);
        float2 f01 = __ldg(&g_feat[lv0][i1]);
        float2 f10 = __ldg(&g_feat[lv1][i0]);
        float2 f11 = __ldg(&g_feat[lv1][i1]);
        a[kt][0] = pack_bf16x2(f00.x, f00.y);
        a[kt][1] = pack_bf16x2(f01.x, f01.y);
        a[kt][2] = pack_bf16x2(f10.x, f10.y);
        a[kt][3] = pack_bf16x2(f11.x, f11.y);
    }
    #pragma unroll
    for (int nt = 0; nt < 8; nt++) {
        d[nt][0] = d[nt][1] = d[nt][2] = d[nt][3] = 0.f;
        #pragma unroll
        for (int kt = 0; kt < 2; kt++) {
            unsigned long long w = s_w0f[(kt * 8 + nt) * 32 + lane];
            mma16816(d[nt], a[kt], (uint32_t)w, (uint32_t)(w >> 32));
        }
    }

    // ---- layers 1 & 2 ----
    #pragma unroll
    for (int layer = 0; layer < 2; layer++) {
        const unsigned long long* s_wf = (layer == 0) ? s_w1f : s_w2f;
        #pragma unroll
        for (int kt = 0; kt < 4; kt++) {
            a[kt][0] = pack_bf16x2(fmaxf(d[2*kt][0], 0.f),   fmaxf(d[2*kt][1], 0.f));
            a[kt][1] = pack_bf16x2(fmaxf(d[2*kt][2], 0.f),   fmaxf(d[2*kt][3], 0.f));
            a[kt][2] = pack_bf16x2(fmaxf(d[2*kt+1][0], 0.f), fmaxf(d[2*kt+1][1], 0.f));
            a[kt][3] = pack_bf16x2(fmaxf(d[2*kt+1][2], 0.f), fmaxf(d[2*kt+1][3], 0.f));
        }
        #pragma unroll
        for (int nt = 0; nt < 8; nt++) {
            d[nt][0] = d[nt][1] = d[nt][2] = d[nt][3] = 0.f;
            #pragma unroll
            for (int kt = 0; kt < 4; kt++) {
                unsigned long long w = s_wf[(kt * 8 + nt) * 32 + lane];
                mma16816(d[nt], a[kt], (uint32_t)w, (uint32_t)(w >> 32));
            }
        }
    }

    // ---- final layer + quad reduce ----
    {
        float o00 = 0.f, o01 = 0.f, o02 = 0.f;
        float o10 = 0.f, o11 = 0.f, o12 = 0.f;
        #pragma unroll
        for (int nt = 0; nt < 8; nt++) {
            int c = nt * 8 + q * 2;
            float h00 = fmaxf(d[nt][0], 0.f), h01 = fmaxf(d[nt][1], 0.f);
            float h10 = fmaxf(d[nt][2], 0.f), h11 = fmaxf(d[nt][3], 0.f);
            float wa0 = s_wo[c],       wb0 = s_wo[c + 1];
            float wa1 = s_wo[64 + c],  wb1 = s_wo[64 + c + 1];
            float wa2 = s_wo[128 + c], wb2 = s_wo[128 + c + 1];
            o00 = fmaf(h00, wa0, fmaf(h01, wb0, o00));
            o01 = fmaf(h00, wa1, fmaf(h01, wb1, o01));
            o02 = fmaf(h00, wa2, fmaf(h01, wb2, o02));
            o10 = fmaf(h10, wa0, fmaf(h11, wb0, o10));
            o11 = fmaf(h10, wa1, fmaf(h11, wb1, o11));
            o12 = fmaf(h10, wa2, fmaf(h11, wb2, o12));
        }
        #pragma unroll
        for (int off = 1; off <= 2; off <<= 1) {
            o00 += __shfl_xor_sync(0xFFFFFFFF, o00, off);
            o01 += __shfl_xor_sync(0xFFFFFFFF, o01, off);
            o02 += __shfl_xor_sync(0xFFFFFFFF, o02, off);
            o10 += __shfl_xor_sync(0xFFFFFFFF, o10, off);
            o11 += __shfl_xor_sync(0xFFFFFFFF, o11, off);
            o12 += __shfl_xor_sync(0xFFFFFFFF, o12, off);
        }
        if (q == 0) {
            const float b0 = s_bo[0], b1 = s_bo[1], b2 = s_bo[2];
            if (v0) {
                size_t ob = (size_t)__ldg(&g_perm[p0]) * 3;
                out[ob + 0] = b0 + o00;
                out[ob + 1] = b1 + o01;
                out[ob + 2] = b2 + o02;
            }
            if (v1) {
                size_t ob = (size_t)__ldg(&g_perm[p1]) * 3;
                out[ob + 0] = b0 + o10;
                out[ob + 1] = b1 + o11;
                out[ob + 2] = b2 + o12;
            }
        }
    }
}

extern "C" void kernel_launch(void* const* d_in, const int* in_sizes, int n_in,
                              void* d_out, int out_size)
{
    const float4* x     = (const float4*)d_in[0];
    const float2* table = (const float2*)d_in[1];
    const float*  w0    = (const float*)d_in[2];
    const float*  w1    = (const float*)d_in[3];
    const float*  w2    = (const float*)d_in[4];
    const float*  w_out = (const float*)d_in[5];
    const float*  b_out = (const float*)d_in[6];
    float* out = (float*)d_out;
    const int N = in_sizes[0] / 4;

    // Replicate numpy's RES computation bit-exactly (same aarch64 glibc pow/floor).
    Res4 res;
    const double minr[4] = {16.0, 16.0, 16.0, 16.0};
    const double maxr[4] = {256.0, 256.0, 256.0, 128.0};
    for (int d = 0; d < 4; d++) {
        double g = pow(maxr[d] / minr[d], 1.0 / 15.0);
        for (int l = 0; l < NLEV; l++) {
            res.v[l][d] = (int)floor(minr[d] * pow(g, (double)l));
        }
    }

    const int pgrid = (N + SBLK - 1) / SBLK;

    prep_weights<<<1, 256>>>(w0, w1, w2);
    sort_zero<<<(NBINS + SBLK - 1) / SBLK, SBLK>>>();
    sort_hist<<<pgrid, SBLK>>>(x, N);
    scan_stage1<<<NSEG, 1024>>>();
    scan_stage2<<<1, NSEG>>>();
    scan_stage3<<<NSEG, 1024>>>();
    sort_scatter<<<pgrid, SBLK>>>(x, N);

    int egrid = (N + EBLK - 1) / EBLK;
    ingp_encode<<<egrid, EBLK>>>(table, N, res);

    int mgrid = (N + 127) / 128;
    ingp_mlp_mma<<<mgrid, 256>>>(w_out, b_out, out, N);
}